// round 4
// baseline (speedup 1.0000x reference)
#include <cuda_runtime.h>

// Problem constants
#define NB   8192
#define NT   16
#define NK   512
#define ND   128

#define TILE_B  128      // rows per CTA
#define KCHUNK  128      // K columns per chunk
#define NCHUNK  (NK / KCHUNK)
#define SZ      130      // padded smem row stride in floats (bank-conflict-free)
#define THREADS 256
#define LOSS_SCALE 1048576.0  // 2^20 fixed-point for deterministic loss sum

using u64 = unsigned long long;

__device__ u64 g_loss;            // fixed-point sum of (z_e - z_q)^2
__device__ int g_used[NT * NK];   // usage bitmap

// Packed fp32x2 FMA (Blackwell FFMA2): d = a*b + c per 32-bit lane
__device__ __forceinline__ u64 ffma2(u64 a, u64 b, u64 c) {
    u64 d;
    asm("fma.rn.f32x2 %0, %1, %2, %3;" : "=l"(d) : "l"(a), "l"(b), "l"(c));
    return d;
}
__device__ __forceinline__ float lo32(u64 v) { return __uint_as_float((unsigned)v); }
__device__ __forceinline__ float hi32(u64 v) { return __uint_as_float((unsigned)(v >> 32)); }

__global__ void vq_init() {
    int tid = threadIdx.x;
    if (tid == 0) g_loss = 0ull;
    for (int i = tid; i < NT * NK; i += blockDim.x) g_used[i] = 0;
}

__global__ __launch_bounds__(THREADS, 1)
void vq_main(const float* __restrict__ z_e, const float* __restrict__ cbk,
             float* __restrict__ out)
{
    extern __shared__ unsigned char smem_raw[];
    double* sred = (double*)smem_raw;                 // 256 doubles (2048 B)
    float*  zs   = (float*)(smem_raw + 2048);         // TILE_B * SZ
    float*  cs   = zs + TILE_B * SZ;                  // KCHUNK * SZ
    float*  zsq  = cs + KCHUNK * SZ;                  // TILE_B
    float*  csq  = zsq + TILE_B;                      // KCHUNK

    const int tid = threadIdx.x;
    const int ttc = tid & 15;        // 16 thread-cols
    const int ttr = tid >> 4;        // 16 thread-rows
    const int t   = blockIdx.y;
    const int b0  = blockIdx.x * TILE_B;

    // ---- load z tile: rows [b0, b0+128) for this t, as float2 ----
    {
        const float* zbase = z_e + (size_t)b0 * (NT * ND) + (size_t)t * ND;
        for (int i = tid; i < TILE_B * (ND / 2); i += THREADS) {
            int r = i >> 6, dp = i & 63;
            float2 v = *(const float2*)(zbase + (size_t)r * (NT * ND) + 2 * dp);
            *(float2*)&zs[r * SZ + 2 * dp] = v;
        }
    }
    __syncthreads();

    // ---- z^2 per row: NEON-style 4-strided accumulation (mimic XLA aarch64),
    //      elementwise mul then add (no FMA contraction) to match reference rounding.
    if (tid < TILE_B) {
        const float* zr = &zs[tid * SZ];
        float s0 = 0.f, s1 = 0.f, s2 = 0.f, s3 = 0.f;
        #pragma unroll 8
        for (int d = 0; d < ND; d += 4) {
            s0 = __fadd_rn(s0, __fmul_rn(zr[d + 0], zr[d + 0]));
            s1 = __fadd_rn(s1, __fmul_rn(zr[d + 1], zr[d + 1]));
            s2 = __fadd_rn(s2, __fmul_rn(zr[d + 2], zr[d + 2]));
            s3 = __fadd_rn(s3, __fmul_rn(zr[d + 3], zr[d + 3]));
        }
        zsq[tid] = __fadd_rn(__fadd_rn(s0, s2), __fadd_rn(s1, s3));
    }
    __syncthreads();

    float z2r[8];
    #pragma unroll
    for (int i = 0; i < 8; i++) z2r[i] = zsq[ttr * 8 + i];

    float best[8];
    int   bkey[8];
    #pragma unroll
    for (int i = 0; i < 8; i++) { best[i] = 3.4e38f; bkey[i] = 0; }

    for (int kc = 0; kc < NCHUNK; kc++) {
        // ---- load codebook chunk [kc*128, kc*128+128) x D ----
        const float* cbase = cbk + (size_t)t * NK * ND + (size_t)kc * KCHUNK * ND;
        for (int i = tid; i < KCHUNK * (ND / 2); i += THREADS) {
            int k = i >> 6, dp = i & 63;
            float2 v = *(const float2*)(cbase + (size_t)k * ND + 2 * dp);
            *(float2*)&cs[k * SZ + 2 * dp] = v;
        }
        __syncthreads();

        // ---- c^2 per chunk row ----
        if (tid < KCHUNK) {
            const float* cr = &cs[tid * SZ];
            float s0 = 0.f, s1 = 0.f, s2 = 0.f, s3 = 0.f;
            #pragma unroll 8
            for (int d = 0; d < ND; d += 4) {
                s0 = __fadd_rn(s0, __fmul_rn(cr[d + 0], cr[d + 0]));
                s1 = __fadd_rn(s1, __fmul_rn(cr[d + 1], cr[d + 1]));
                s2 = __fadd_rn(s2, __fmul_rn(cr[d + 2], cr[d + 2]));
                s3 = __fadd_rn(s3, __fmul_rn(cr[d + 3], cr[d + 3]));
            }
            csq[tid] = __fadd_rn(__fadd_rn(s0, s2), __fadd_rn(s1, s3));
        }
        __syncthreads();

        // ---- main GEMM: 8x8 register tile, d packed 2-wide into FFMA2 ----
        u64 acc[8][8];
        #pragma unroll
        for (int i = 0; i < 8; i++)
            #pragma unroll
            for (int j = 0; j < 8; j++) acc[i][j] = 0ull;

        const float* zb = &zs[(ttr * 8) * SZ];
        const float* cb = &cs[ttc * SZ];

        #pragma unroll 4
        for (int dp = 0; dp < ND / 2; dp++) {
            u64 zv[8], cv[8];
            #pragma unroll
            for (int i = 0; i < 8; i++)
                zv[i] = *(const u64*)(zb + i * SZ + 2 * dp);
            #pragma unroll
            for (int j = 0; j < 8; j++)
                cv[j] = *(const u64*)(cb + j * 16 * SZ + 2 * dp);
            #pragma unroll
            for (int i = 0; i < 8; i++)
                #pragma unroll
                for (int j = 0; j < 8; j++)
                    acc[i][j] = ffma2(zv[i], cv[j], acc[i][j]);
        }

        // ---- distances + running argmin (first-index ties via strict <) ----
        #pragma unroll
        for (int j = 0; j < 8; j++) {
            float c2 = csq[ttc + 16 * j];
            int   kk = kc * KCHUNK + ttc + 16 * j;
            #pragma unroll
            for (int i = 0; i < 8; i++) {
                float dot  = __fadd_rn(lo32(acc[i][j]), hi32(acc[i][j]));
                float s    = __fsub_rn(z2r[i], 2.0f * dot);   // 2*dot exact
                float dist = __fadd_rn(s, c2);                // matches (z2-2E)+c2 rounding
                if (dist < best[i]) { best[i] = dist; bkey[i] = kk; }
            }
        }
        __syncthreads();   // before next chunk overwrites cs
    }

    // ---- per-row reduction across the 16 thread-cols + epilogue ----
    double lsum = 0.0;
    #pragma unroll 1
    for (int i = 0; i < 8; i++) {
        float bd = best[i];
        int   bk = bkey[i];
        #pragma unroll
        for (int off = 8; off >= 1; off >>= 1) {
            float od = __shfl_down_sync(0xffffffffu, bd, off, 16);
            int   ok = __shfl_down_sync(0xffffffffu, bk, off, 16);
            if (od < bd || (od == bd && ok < bk)) { bd = od; bk = ok; }
        }
        bk = __shfl_sync(0xffffffffu, bk, 0, 16);  // broadcast winner

        int row = ttr * 8 + i;
        int b   = b0 + row;
        if (ttc == 0) {
            out[(size_t)NB * NT * ND + (size_t)b * NT + t] = (float)bk;
            g_used[t * NK + bk] = 1;   // idempotent racy store of 1
        }

        const float* crow = cbk + (size_t)t * NK * ND + (size_t)bk * ND + ttc * 8;
        const float* zrow = &zs[row * SZ + ttc * 8];
        float o[8];
        #pragma unroll
        for (int d = 0; d < 8; d++) {
            float zz = zrow[d], cc = crow[d];
            o[d] = __fadd_rn(zz, __fsub_rn(cc, zz));  // z_e + (z_q - z_e), ref rounding
            float df = __fsub_rn(zz, cc);
            lsum += (double)__fmul_rn(df, df);
        }
        float4* op = (float4*)(out + (size_t)b * (NT * ND) + (size_t)t * ND + ttc * 8);
        op[0] = make_float4(o[0], o[1], o[2], o[3]);
        op[1] = make_float4(o[4], o[5], o[6], o[7]);
    }

    // ---- CTA loss reduction (fixed tree, deterministic), one u64 atomic per CTA ----
    sred[tid] = lsum;
    __syncthreads();
    for (int s = 128; s > 0; s >>= 1) {
        if (tid < s) sred[tid] += sred[tid + s];
        __syncthreads();
    }
    if (tid == 0) {
        long long q = __double2ll_rn(sred[0] * LOSS_SCALE);
        atomicAdd(&g_loss, (u64)q);
    }
}

__global__ void vq_fin(float* __restrict__ out) {
    __shared__ int cnt[256];
    int tid = threadIdx.x;
    int c = 0;
    for (int i = tid; i < NT * NK; i += 256) c += g_used[i];
    cnt[tid] = c;
    __syncthreads();
    for (int s = 128; s > 0; s >>= 1) {
        if (tid < s) cnt[tid] += cnt[tid + s];
        __syncthreads();
    }
    if (tid == 0) {
        double ls = (double)g_loss / LOSS_SCALE;
        float vql = (float)(0.25 * ls / ((double)NB * NT * ND));
        size_t base = (size_t)NB * NT * ND + (size_t)NB * NT;
        out[base]     = vql;
        out[base + 1] = (float)cnt[0] / (float)(NT * NK);
    }
}

extern "C" void kernel_launch(void* const* d_in, const int* in_sizes, int n_in,
                              void* d_out, int out_size)
{
    const float* z_e = (const float*)d_in[0];   // (B, T, D) fp32
    const float* cbk = (const float*)d_in[1];   // (T, K, D) fp32
    float* out = (float*)d_out;                 // [z_q_st | tokens | vq_loss | util]

    const int smem_bytes = 2048 + (TILE_B * SZ + KCHUNK * SZ + TILE_B + KCHUNK) * (int)sizeof(float);
    cudaFuncSetAttribute(vq_main, cudaFuncAttributeMaxDynamicSharedMemorySize, smem_bytes);

    vq_init<<<1, 256>>>();
    vq_main<<<dim3(NB / TILE_B, NT), THREADS, smem_bytes>>>(z_e, cbk, out);
    vq_fin<<<1, 256>>>(out);
}